// round 2
// baseline (speedup 1.0000x reference)
#include <cuda_runtime.h>
#include <math.h>

#define S_    4096
#define D_    768
#define H_    12
#define HD_   64
#define NCLS_ 64
#define FF_   3072
#define WIN_  256
#define NWIN_ 513           /* 2*WIN+1 */
#define NKEY_ (NCLS_ + NWIN_)   /* 577 */
#define LAYERS_ 2

// ---------------- scratch (static device globals; no allocation) ----------------
__device__ float g_h  [S_*D_];
__device__ float g_q  [S_*D_];
__device__ float g_k  [S_*D_];
__device__ float g_v  [S_*D_];
__device__ float g_kg [S_*D_];
__device__ float g_vg [S_*D_];
__device__ float g_out[S_*D_];
__device__ float g_tmp[S_*D_];
__device__ float g_ff [S_*FF_];
__device__ float g_hg [NCLS_*D_];
__device__ float g_qg [NCLS_*D_];
__device__ int   g_glb[S_];

// ---------------- SGEMM: C = A(MxK) @ B(KxN) + bias, optional gelu ----------------
__global__ __launch_bounds__(256) void sgemm_kernel(
    const float* __restrict__ A, const float* __restrict__ B,
    const float* __restrict__ bias, float* __restrict__ C,
    int M, int N, int K, int act)
{
    __shared__ float As[8][128];
    __shared__ float Bs[8][128];
    const int tid = threadIdx.x;
    const int tx = tid & 15;
    const int ty = tid >> 4;
    const int blockRow = blockIdx.y * 128;
    const int blockCol = blockIdx.x * 128;
    const int aRow = tid >> 1;
    const int aCol = (tid & 1) << 2;
    const int bRow = tid >> 5;
    const int bCol = (tid & 31) << 2;
    float acc[8][8];
#pragma unroll
    for (int i = 0; i < 8; i++)
#pragma unroll
        for (int j = 0; j < 8; j++) acc[i][j] = 0.f;

    for (int k0 = 0; k0 < K; k0 += 8) {
        int gr = blockRow + aRow;
        float4 av = make_float4(0.f, 0.f, 0.f, 0.f);
        if (gr < M)
            av = *reinterpret_cast<const float4*>(A + (size_t)gr * K + k0 + aCol);
        As[aCol + 0][aRow] = av.x;
        As[aCol + 1][aRow] = av.y;
        As[aCol + 2][aRow] = av.z;
        As[aCol + 3][aRow] = av.w;
        float4 bv = *reinterpret_cast<const float4*>(B + (size_t)(k0 + bRow) * N + blockCol + bCol);
        *reinterpret_cast<float4*>(&Bs[bRow][bCol]) = bv;
        __syncthreads();
#pragma unroll
        for (int kk = 0; kk < 8; kk++) {
            float a[8], b[8];
            *reinterpret_cast<float4*>(a)     = *reinterpret_cast<const float4*>(&As[kk][ty * 8]);
            *reinterpret_cast<float4*>(a + 4) = *reinterpret_cast<const float4*>(&As[kk][ty * 8 + 4]);
            *reinterpret_cast<float4*>(b)     = *reinterpret_cast<const float4*>(&Bs[kk][tx * 8]);
            *reinterpret_cast<float4*>(b + 4) = *reinterpret_cast<const float4*>(&Bs[kk][tx * 8 + 4]);
#pragma unroll
            for (int i = 0; i < 8; i++)
#pragma unroll
                for (int j = 0; j < 8; j++) acc[i][j] = fmaf(a[i], b[j], acc[i][j]);
        }
        __syncthreads();
    }
#pragma unroll
    for (int i = 0; i < 8; i++) {
        int r = blockRow + ty * 8 + i;
        if (r >= M) continue;
#pragma unroll
        for (int j = 0; j < 8; j++) {
            int c = blockCol + tx * 8 + j;
            float val = acc[i][j] + bias[c];
            if (act == 1) {
                float u = 0.7978845608028654f * (val + 0.044715f * val * val * val);
                val = 0.5f * val * (1.f + tanhf(u));
            }
            C[(size_t)r * N + c] = val;
        }
    }
}

// ---------------- embedding + layernorm ----------------
__global__ __launch_bounds__(256) void embed_ln_kernel(
    const int* __restrict__ x, const int* __restrict__ segs,
    const float* __restrict__ we, const float* __restrict__ pe, const float* __restrict__ te,
    const float* __restrict__ lns, const float* __restrict__ lnb,
    float* __restrict__ hout)
{
    int s = blockIdx.x;
    int tid = threadIdx.x;
    __shared__ float buf[D_];
    __shared__ float red[256];
    int tok = x[s], seg = segs[s];
    float lsum = 0.f;
    for (int d = tid; d < D_; d += 256) {
        float v = we[(size_t)tok * D_ + d] + pe[(size_t)s * D_ + d] + te[(size_t)seg * D_ + d];
        buf[d] = v;
        lsum += v;
    }
    red[tid] = lsum; __syncthreads();
    for (int o = 128; o > 0; o >>= 1) { if (tid < o) red[tid] += red[tid + o]; __syncthreads(); }
    float mean = red[0] / D_;
    __syncthreads();
    float vsum = 0.f;
    for (int d = tid; d < D_; d += 256) { float t = buf[d] - mean; vsum += t * t; }
    red[tid] = vsum; __syncthreads();
    for (int o = 128; o > 0; o >>= 1) { if (tid < o) red[tid] += red[tid + o]; __syncthreads(); }
    float rstd = rsqrtf(red[0] / D_ + 1e-5f);
    for (int d = tid; d < D_; d += 256)
        hout[(size_t)s * D_ + d] = (buf[d] - mean) * rstd * lns[d] + lnb[d];
}

// ---------------- residual add + layernorm (in-place into h) ----------------
__global__ __launch_bounds__(256) void add_ln_kernel(
    float* __restrict__ h, const float* __restrict__ t,
    const float* __restrict__ lns, const float* __restrict__ lnb)
{
    int s = blockIdx.x;
    int tid = threadIdx.x;
    __shared__ float buf[D_];
    __shared__ float red[256];
    float lsum = 0.f;
    for (int d = tid; d < D_; d += 256) {
        float v = h[(size_t)s * D_ + d] + t[(size_t)s * D_ + d];
        buf[d] = v;
        lsum += v;
    }
    red[tid] = lsum; __syncthreads();
    for (int o = 128; o > 0; o >>= 1) { if (tid < o) red[tid] += red[tid + o]; __syncthreads(); }
    float mean = red[0] / D_;
    __syncthreads();
    float vsum = 0.f;
    for (int d = tid; d < D_; d += 256) { float x = buf[d] - mean; vsum += x * x; }
    red[tid] = vsum; __syncthreads();
    for (int o = 128; o > 0; o >>= 1) { if (tid < o) red[tid] += red[tid + o]; __syncthreads(); }
    float rstd = rsqrtf(red[0] / D_ + 1e-5f);
    for (int d = tid; d < D_; d += 256)
        h[(size_t)s * D_ + d] = (buf[d] - mean) * rstd * lns[d] + lnb[d];
}

// ---------------- global flags ----------------
__global__ void zero_flags_kernel(int* f)
{
    int i = blockIdx.x * 256 + threadIdx.x;
    if (i < S_) f[i] = 0;
}
__global__ void set_flags_kernel(const int* __restrict__ clss, int* f)
{
    if (threadIdx.x < NCLS_) f[clss[threadIdx.x]] = 1;
}
__global__ __launch_bounds__(256) void gather_rows_kernel(
    const float* __restrict__ h, const int* __restrict__ clss, float* __restrict__ hg)
{
    int c = blockIdx.x;
    int gp = clss[c];
    for (int d = threadIdx.x; d < D_; d += 256)
        hg[(size_t)c * D_ + d] = h[(size_t)gp * D_ + d];
}

// ---------------- band + global-key attention: one block per (s, head) ----------------
__global__ __launch_bounds__(128) void band_attn_kernel(
    const float* __restrict__ q, const float* __restrict__ k, const float* __restrict__ v,
    const int* __restrict__ clss, const int* __restrict__ mask_src, const int* __restrict__ glb,
    float* __restrict__ out)
{
    const int s = blockIdx.x;
    const int h = blockIdx.y;
    __shared__ float qs[HD_];
    __shared__ float sc[NKEY_];
    __shared__ int   pos[NKEY_];
    __shared__ float red[128];
    const int tid = threadIdx.x;
    const int lane = tid & 31;
    const int w = tid >> 5;

    if (tid < HD_) qs[tid] = q[((size_t)s * H_ + h) * HD_ + tid] * 0.125f;
    __syncthreads();

    // scores: [0,64) = global keys, [64,577) = window keys p = s-256+(i-64)
    for (int i = w; i < NKEY_; i += 4) {
        int p; bool valid;
        if (i < NCLS_) {
            p = clss[i];
            valid = (mask_src[p] > 0);
        } else {
            p = s - WIN_ + (i - NCLS_);
            valid = (p >= 0 && p < S_ && mask_src[p] > 0 && glb[p] == 0);
        }
        float sdot = 0.f;
        if (valid) {
            const float* kp = k + ((size_t)p * H_ + h) * HD_;
            sdot = qs[lane] * kp[lane] + qs[lane + 32] * kp[lane + 32];
#pragma unroll
            for (int o = 16; o > 0; o >>= 1) sdot += __shfl_xor_sync(0xffffffffu, sdot, o);
        }
        if (lane == 0) { sc[i] = valid ? sdot : -1e30f; pos[i] = valid ? p : -1; }
    }
    __syncthreads();

    // softmax
    float m = -1e30f;
    for (int i = tid; i < NKEY_; i += 128) m = fmaxf(m, sc[i]);
    red[tid] = m; __syncthreads();
    for (int o = 64; o > 0; o >>= 1) { if (tid < o) red[tid] = fmaxf(red[tid], red[tid + o]); __syncthreads(); }
    m = red[0];
    __syncthreads();
    float sum = 0.f;
    for (int i = tid; i < NKEY_; i += 128) {
        float e = __expf(sc[i] - m);   // invalid: exp(-1e30 - m) underflows to 0
        sc[i] = e;
        sum += e;
    }
    red[tid] = sum; __syncthreads();
    for (int o = 64; o > 0; o >>= 1) { if (tid < o) red[tid] += red[tid + o]; __syncthreads(); }
    float inv = 1.f / red[0];
    __syncthreads();

    // output: threads split keys into 2 halves, each owns one dim
    int d = tid & 63, half = tid >> 6;
    float acc = 0.f;
    for (int i = half; i < NKEY_; i += 2) {
        int p = pos[i];
        if (p >= 0) acc += sc[i] * v[((size_t)p * H_ + h) * HD_ + d];
    }
    red[tid] = acc; __syncthreads();
    if (tid < 64)
        out[((size_t)s * H_ + h) * HD_ + tid] = (red[tid] + red[tid + 64]) * inv;
}

// ---------------- global-query full attention: one block per (c, head) ----------------
__global__ __launch_bounds__(256) void glb_attn_kernel(
    const float* __restrict__ qg, const float* __restrict__ kg, const float* __restrict__ vg,
    const int* __restrict__ clss, const int* __restrict__ mask_src,
    float* __restrict__ out)
{
    const int c = blockIdx.x;
    const int h = blockIdx.y;
    __shared__ float qs[HD_];
    __shared__ float sc[S_];
    __shared__ float red[256];
    const int tid = threadIdx.x;
    const int lane = tid & 31;
    const int w = tid >> 5;

    if (tid < HD_) qs[tid] = qg[((size_t)c * H_ + h) * HD_ + tid] * 0.125f;
    __syncthreads();

    for (int p = w; p < S_; p += 8) {
        const float* kp = kg + ((size_t)p * H_ + h) * HD_;
        float sdot = qs[lane] * kp[lane] + qs[lane + 32] * kp[lane + 32];
#pragma unroll
        for (int o = 16; o > 0; o >>= 1) sdot += __shfl_xor_sync(0xffffffffu, sdot, o);
        if (lane == 0) sc[p] = (mask_src[p] > 0) ? sdot : -1e30f;
    }
    __syncthreads();

    float m = -1e30f;
    for (int p = tid; p < S_; p += 256) m = fmaxf(m, sc[p]);
    red[tid] = m; __syncthreads();
    for (int o = 128; o > 0; o >>= 1) { if (tid < o) red[tid] = fmaxf(red[tid], red[tid + o]); __syncthreads(); }
    m = red[0];
    __syncthreads();
    float sum = 0.f;
    for (int p = tid; p < S_; p += 256) { float e = __expf(sc[p] - m); sc[p] = e; sum += e; }
    red[tid] = sum; __syncthreads();
    for (int o = 128; o > 0; o >>= 1) { if (tid < o) red[tid] += red[tid + o]; __syncthreads(); }
    float inv = 1.f / red[0];
    __syncthreads();

    int d = tid & 63, quarter = tid >> 6;
    float acc = 0.f;
    for (int p = quarter; p < S_; p += 4)
        acc += sc[p] * vg[((size_t)p * H_ + h) * HD_ + d];
    red[tid] = acc; __syncthreads();
    if (tid < 64) {
        float o = (red[tid] + red[tid + 64] + red[tid + 128] + red[tid + 192]) * inv;
        int gp = clss[c];
        out[((size_t)gp * H_ + h) * HD_ + tid] = o;   // duplicate c -> identical value, benign
    }
}

// ---------------- driver ----------------
static void run_gemm(const float* A, const float* B, const float* bias, float* C,
                     int M, int N, int K, int act)
{
    dim3 grid(N / 128, (M + 127) / 128);
    sgemm_kernel<<<grid, 256>>>(A, B, bias, C, M, N, K, act);
}

extern "C" void kernel_launch(void* const* d_in, const int* in_sizes, int n_in,
                              void* d_out, int out_size)
{
    (void)in_sizes; (void)n_in;
    const int*   x        = (const int*)d_in[0];
    const int*   mask_src = (const int*)d_in[1];
    const int*   clss     = (const int*)d_in[2];
    const int*   segs     = (const int*)d_in[3];
    const float* word_emb = (const float*)d_in[4];
    const float* pos_emb  = (const float*)d_in[5];
    const float* type_emb = (const float*)d_in[6];
    const float* ln_e_s   = (const float*)d_in[7];
    const float* ln_e_b   = (const float*)d_in[8];
    const float* Wq  = (const float*)d_in[9];   const float* bq  = (const float*)d_in[10];
    const float* Wk  = (const float*)d_in[11];  const float* bk  = (const float*)d_in[12];
    const float* Wv  = (const float*)d_in[13];  const float* bv  = (const float*)d_in[14];
    const float* Wqg = (const float*)d_in[15];  const float* bqg = (const float*)d_in[16];
    const float* Wkg = (const float*)d_in[17];  const float* bkg = (const float*)d_in[18];
    const float* Wvg = (const float*)d_in[19];  const float* bvg = (const float*)d_in[20];
    const float* Wo  = (const float*)d_in[21];  const float* bo  = (const float*)d_in[22];
    const float* ln1_s = (const float*)d_in[23]; const float* ln1_b = (const float*)d_in[24];
    const float* Wf1 = (const float*)d_in[25];  const float* bf1 = (const float*)d_in[26];
    const float* Wf2 = (const float*)d_in[27];  const float* bf2 = (const float*)d_in[28];
    const float* ln2_s = (const float*)d_in[29]; const float* ln2_b = (const float*)d_in[30];

    float *h, *q, *k, *v, *kg, *vg, *outb, *tmp, *ff, *hg, *qg;
    int* glb;
    cudaGetSymbolAddress((void**)&h,    g_h);
    cudaGetSymbolAddress((void**)&q,    g_q);
    cudaGetSymbolAddress((void**)&k,    g_k);
    cudaGetSymbolAddress((void**)&v,    g_v);
    cudaGetSymbolAddress((void**)&kg,   g_kg);
    cudaGetSymbolAddress((void**)&vg,   g_vg);
    cudaGetSymbolAddress((void**)&outb, g_out);
    cudaGetSymbolAddress((void**)&tmp,  g_tmp);
    cudaGetSymbolAddress((void**)&ff,   g_ff);
    cudaGetSymbolAddress((void**)&hg,   g_hg);
    cudaGetSymbolAddress((void**)&qg,   g_qg);
    cudaGetSymbolAddress((void**)&glb,  g_glb);

    // embedding + LN
    embed_ln_kernel<<<S_, 256>>>(x, segs, word_emb, pos_emb, type_emb, ln_e_s, ln_e_b, h);

    // global flags
    zero_flags_kernel<<<(S_ + 255) / 256, 256>>>(glb);
    set_flags_kernel<<<1, 64>>>(clss, glb);

    const size_t DD = (size_t)D_ * D_;
    for (int l = 0; l < LAYERS_; l++) {
        // Q K V projections
        run_gemm(h, Wq + l * DD, bq + l * D_, q, S_, D_, D_, 0);
        run_gemm(h, Wk + l * DD, bk + l * D_, k, S_, D_, D_, 0);
        run_gemm(h, Wv + l * DD, bv + l * D_, v, S_, D_, D_, 0);

        // band + global-key attention (writes all rows of outb)
        band_attn_kernel<<<dim3(S_, H_), 128>>>(q, k, v, clss, mask_src, glb, outb);

        // global-query path
        gather_rows_kernel<<<NCLS_, 256>>>(h, clss, hg);
        run_gemm(hg, Wqg + l * DD, bqg + l * D_, qg, NCLS_, D_, D_, 0);
        run_gemm(h,  Wkg + l * DD, bkg + l * D_, kg, S_, D_, D_, 0);
        run_gemm(h,  Wvg + l * DD, bvg + l * D_, vg, S_, D_, D_, 0);
        glb_attn_kernel<<<dim3(NCLS_, H_), 256>>>(qg, kg, vg, clss, mask_src, outb);

        // output projection + residual LN
        run_gemm(outb, Wo + l * DD, bo + l * D_, tmp, S_, D_, D_, 0);
        add_ln_kernel<<<S_, 256>>>(h, tmp, ln1_s + l * D_, ln1_b + l * D_);

        // feed-forward
        run_gemm(h,  Wf1 + (size_t)l * D_ * FF_, bf1 + l * FF_, ff,  S_, FF_, D_, 1);
        run_gemm(ff, Wf2 + (size_t)l * D_ * FF_, bf2 + l * D_,  tmp, S_, D_, FF_, 0);
        add_ln_kernel<<<S_, 256>>>(h, tmp, ln2_s + l * D_, ln2_b + l * D_);
    }

    cudaMemcpyAsync(d_out, h, (size_t)out_size * sizeof(float), cudaMemcpyDeviceToDevice);
}